// round 6
// baseline (speedup 1.0000x reference)
#include <cuda_runtime.h>
#include <cuda_bf16.h>
#include <cstdint>

#define T_SEQ 4096
#define C_DIM 1024
#define NH    16
#define DHEAD 64
#define BANDW 128

typedef __nv_bfloat16  bf16;
typedef __nv_bfloat162 bf162;

// ---------------------------------------------------------------------------
// Scratch (__device__ globals; allocation-free rule)
// ---------------------------------------------------------------------------
__device__ bf16 g_xhi[T_SEQ * C_DIM];
__device__ bf16 g_xlo[T_SEQ * C_DIM];
__device__ bf16 g_qhi[T_SEQ * C_DIM];
__device__ bf16 g_qlo[T_SEQ * C_DIM];
__device__ bf16 g_khi[T_SEQ * C_DIM];
__device__ bf16 g_klo[T_SEQ * C_DIM];
__device__ bf16 g_vhi[T_SEQ * C_DIM];
__device__ bf16 g_vlo[T_SEQ * C_DIM];
__device__ bf16 g_ahi[T_SEQ * C_DIM];
__device__ bf16 g_alo[T_SEQ * C_DIM];
__device__ bf16 g_whi[4][C_DIM * C_DIM];
__device__ bf16 g_wlo[4][C_DIM * C_DIM];

// ---------------------------------------------------------------------------
// PTX helpers (base features only — compute_103 PTX target)
// ---------------------------------------------------------------------------
__device__ __forceinline__ uint32_t smem_u32(const void* p) {
    uint32_t a;
    asm("{ .reg .u64 t; cvta.to.shared.u64 t, %1; cvt.u32.u64 %0, t; }" : "=r"(a) : "l"(p));
    return a;
}
__device__ __forceinline__ void cp16(uint32_t dst, const void* src) {
    asm volatile("cp.async.cg.shared.global [%0], [%1], 16;" :: "r"(dst), "l"(src));
}
__device__ __forceinline__ void cp_commit() {
    asm volatile("cp.async.commit_group;" ::: "memory");
}
__device__ __forceinline__ void stz16(uint32_t a) {
    asm volatile("st.shared.v4.u32 [%0], {%1,%1,%1,%1};" :: "r"(a), "r"(0) : "memory");
}
__device__ __forceinline__ void ldm_x4(uint32_t* r, uint32_t a) {
    asm volatile("ldmatrix.sync.aligned.m8n8.x4.shared.b16 {%0,%1,%2,%3}, [%4];"
                 : "=r"(r[0]), "=r"(r[1]), "=r"(r[2]), "=r"(r[3]) : "r"(a));
}
__device__ __forceinline__ void ldm_x4t(uint32_t* r, uint32_t a) {
    asm volatile("ldmatrix.sync.aligned.m8n8.x4.trans.shared.b16 {%0,%1,%2,%3}, [%4];"
                 : "=r"(r[0]), "=r"(r[1]), "=r"(r[2]), "=r"(r[3]) : "r"(a));
}
__device__ __forceinline__ void mma16816(float* d, const uint32_t* a, const uint32_t* b) {
    asm volatile("mma.sync.aligned.m16n8k16.row.col.f32.bf16.bf16.f32 "
                 "{%0,%1,%2,%3}, {%4,%5,%6,%7}, {%8,%9}, {%0,%1,%2,%3};"
                 : "+f"(d[0]), "+f"(d[1]), "+f"(d[2]), "+f"(d[3])
                 : "r"(a[0]), "r"(a[1]), "r"(a[2]), "r"(a[3]), "r"(b[0]), "r"(b[1]));
}
__device__ __forceinline__ void split2(float x, bf16& h, bf16& l) {
    h = __float2bfloat16(x);
    l = __float2bfloat16(x - __bfloat162float(h));
}

// ---------------------------------------------------------------------------
// fp32 -> (hi, lo) bf16 split kernels
// ---------------------------------------------------------------------------
__global__ __launch_bounds__(256) void split_kernel(const float* __restrict__ in,
                                                    bf16* __restrict__ hi,
                                                    bf16* __restrict__ lo, int n4) {
    int i = blockIdx.x * 256 + threadIdx.x;
    if (i >= n4) return;
    float4 v = ((const float4*)in)[i];
    bf16 h0, h1, h2, h3, l0, l1, l2, l3;
    split2(v.x, h0, l0); split2(v.y, h1, l1); split2(v.z, h2, l2); split2(v.w, h3, l3);
    bf162* hp = (bf162*)(hi + 4 * (size_t)i);
    bf162* lp = (bf162*)(lo + 4 * (size_t)i);
    hp[0] = bf162(h0, h1); hp[1] = bf162(h2, h3);
    lp[0] = bf162(l0, l1); lp[1] = bf162(l2, l3);
}

__global__ __launch_bounds__(256) void split_w4_kernel(const float* __restrict__ w0,
                                                       const float* __restrict__ w1,
                                                       const float* __restrict__ w2,
                                                       const float* __restrict__ w3,
                                                       bf16* __restrict__ hi,
                                                       bf16* __restrict__ lo, int n4) {
    int i = blockIdx.x * 256 + threadIdx.x;
    if (i >= n4) return;
    int wsel = blockIdx.y;
    const float* in = (wsel == 0) ? w0 : (wsel == 1) ? w1 : (wsel == 2) ? w2 : w3;
    size_t base = (size_t)wsel * (C_DIM * C_DIM);
    float4 v = ((const float4*)in)[i];
    bf16 h0, h1, h2, h3, l0, l1, l2, l3;
    split2(v.x, h0, l0); split2(v.y, h1, l1); split2(v.z, h2, l2); split2(v.w, h3, l3);
    bf162* hp = (bf162*)(hi + base + 4 * (size_t)i);
    bf162* lp = (bf162*)(lo + base + 4 * (size_t)i);
    hp[0] = bf162(h0, h1); hp[1] = bf162(h2, h3);
    lp[0] = bf162(l0, l1); lp[1] = bf162(l2, l3);
}

// ---------------------------------------------------------------------------
// Shared GEMM mainloop (bf16 hi/lo, 3-pass): 128x128 CTA tile, BK=16,
// 256 threads = 2x4 warps (warp tile 64x32), 4-stage cp.async ring,
// one __syncthreads per chunk, 48B padded rows (conflict-free ldmatrix),
// 98.3KB smem -> 2 CTAs/SM.
// ---------------------------------------------------------------------------
#define BM 128
#define BN 128
#define BK 16
#define GK C_DIM
#define NCHUNK (GK / BK)          // 64
#define ROWB 48                   // 16 bf16 = 32B data + 16B pad
#define TILEB (128 * ROWB)        // 6144 B
#define STAGEB (4 * TILEB)        // 24576 B
#define NSTAGE 4
#define GEMM_SMEM (NSTAGE * STAGEB)   // 98304 B

__device__ __forceinline__ void gemm_mainloop(uint32_t sbase, int tid,
                                              const bf16* __restrict__ tA_hi,
                                              const bf16* __restrict__ tA_lo,
                                              const bf16* __restrict__ tB_hi,
                                              const bf16* __restrict__ tB_lo,
                                              float (&acc)[4][4][4]) {
    const int lane = tid & 31;
    const int warp = tid >> 5;
    const int warp_m = warp >> 2;
    const int warp_n = warp & 3;
    const int r0 = tid >> 1;           // 0..127
    const int q  = tid & 1;            // 16B half of 32B row
    const bf16* tb[4] = {tA_hi, tA_lo, tB_hi, tB_lo};

    auto load_stage = [&](int s, int c) {
        const int k0 = c * BK;
        const uint32_t ds = sbase + s * STAGEB;
#pragma unroll
        for (int t = 0; t < 4; t++)
            cp16(ds + t * TILEB + r0 * ROWB + q * 16,
                 tb[t] + (size_t)r0 * GK + k0 + q * 8);
        cp_commit();
    };

    const int sel = lane >> 3;
    const int l7  = lane & 7;
    const uint32_t aoff = (uint32_t)((warp_m * 64 + (sel & 1) * 8 + l7) * ROWB + (sel >> 1) * 16);
    const uint32_t boff = (uint32_t)((warp_n * 32 + (sel >> 1) * 8 + l7) * ROWB + (sel & 1) * 16);

    load_stage(0, 0);
    load_stage(1, 1);
    load_stage(2, 2);

    for (int c = 0; c < NCHUNK; c++) {
        const int pend = NCHUNK - 1 - c;
        if (pend >= 2)      asm volatile("cp.async.wait_group 2;" ::: "memory");
        else if (pend == 1) asm volatile("cp.async.wait_group 1;" ::: "memory");
        else                asm volatile("cp.async.wait_group 0;" ::: "memory");
        __syncthreads();

        if (c + 3 < NCHUNK) load_stage((c + 3) & 3, c + 3);

        const uint32_t ds = sbase + (c & 3) * STAGEB;
        const uint32_t sAh = ds + 0 * TILEB + aoff;
        const uint32_t sAl = ds + 1 * TILEB + aoff;
        const uint32_t sBh = ds + 2 * TILEB + boff;
        const uint32_t sBl = ds + 3 * TILEB + boff;

        uint32_t Ah[4][4], Al[4][4], Bh[4][2], Bl[4][2];
#pragma unroll
        for (int mt = 0; mt < 4; mt++) {
            ldm_x4(Ah[mt], sAh + mt * (16 * ROWB));
            ldm_x4(Al[mt], sAl + mt * (16 * ROWB));
        }
#pragma unroll
        for (int p = 0; p < 2; p++) {
            uint32_t rh[4], rl[4];
            ldm_x4(rh, sBh + p * (16 * ROWB));
            ldm_x4(rl, sBl + p * (16 * ROWB));
            Bh[2 * p][0] = rh[0]; Bh[2 * p][1] = rh[1];
            Bh[2 * p + 1][0] = rh[2]; Bh[2 * p + 1][1] = rh[3];
            Bl[2 * p][0] = rl[0]; Bl[2 * p][1] = rl[1];
            Bl[2 * p + 1][0] = rl[2]; Bl[2 * p + 1][1] = rl[3];
        }
#pragma unroll
        for (int mt = 0; mt < 4; mt++)
#pragma unroll
            for (int nt = 0; nt < 4; nt++)
                mma16816(acc[mt][nt], Ah[mt], Bh[nt]);
#pragma unroll
        for (int mt = 0; mt < 4; mt++)
#pragma unroll
            for (int nt = 0; nt < 4; nt++)
                mma16816(acc[mt][nt], Ah[mt], Bl[nt]);
#pragma unroll
        for (int mt = 0; mt < 4; mt++)
#pragma unroll
            for (int nt = 0; nt < 4; nt++)
                mma16816(acc[mt][nt], Al[mt], Bh[nt]);
    }
}

// ---- Fused QKV projection: epilogue emits bf16 hi/lo ----
__global__ __launch_bounds__(256, 2) void mma_gemm_qkv(const bf16* __restrict__ xhi,
                                                       const bf16* __restrict__ xlo,
                                                       const bf16* __restrict__ whi,
                                                       const bf16* __restrict__ wlo,
                                                       bf16* __restrict__ qhi, bf16* __restrict__ qlo,
                                                       bf16* __restrict__ khi, bf16* __restrict__ klo,
                                                       bf16* __restrict__ vhi, bf16* __restrict__ vlo) {
    extern __shared__ __align__(128) char smem[];
    const uint32_t sbase = smem_u32(smem);
    const int tid = threadIdx.x;
    const int which = blockIdx.x >> 3;
    const int n0 = (blockIdx.x & 7) * BN;
    const int m0 = blockIdx.y * BM;
    const size_t WSZ = (size_t)C_DIM * C_DIM;

    float acc[4][4][4];
#pragma unroll
    for (int i = 0; i < 4; i++)
#pragma unroll
        for (int j = 0; j < 4; j++)
#pragma unroll
            for (int e = 0; e < 4; e++) acc[i][j][e] = 0.0f;

    gemm_mainloop(sbase, tid,
                  xhi + (size_t)m0 * GK, xlo + (size_t)m0 * GK,
                  whi + which * WSZ + (size_t)n0 * GK,
                  wlo + which * WSZ + (size_t)n0 * GK, acc);

    bf16* oh = (which == 0) ? qhi : (which == 1) ? khi : vhi;
    bf16* ol = (which == 0) ? qlo : (which == 1) ? klo : vlo;

    const int lane = tid & 31;
    const int warp = tid >> 5;
    const int warp_m = warp >> 2;
    const int warp_n = warp & 3;
    const int er = lane >> 2;
    const int ec = (lane & 3) * 2;
#pragma unroll
    for (int mt = 0; mt < 4; mt++) {
        const int row = m0 + warp_m * 64 + mt * 16 + er;
#pragma unroll
        for (int nt = 0; nt < 4; nt++) {
            const int col = n0 + warp_n * 32 + nt * 8 + ec;
#pragma unroll
            for (int hh = 0; hh < 2; hh++) {
                float c0 = acc[mt][nt][2 * hh], c1 = acc[mt][nt][2 * hh + 1];
                bf16 h0, h1, l0, l1;
                split2(c0, h0, l0); split2(c1, h1, l1);
                size_t off = (size_t)(row + 8 * hh) * C_DIM + col;
                *(bf162*)&oh[off] = bf162(h0, h1);
                *(bf162*)&ol[off] = bf162(l0, l1);
            }
        }
    }
}

// ---- Output projection: fp32 epilogue ----
__global__ __launch_bounds__(256, 2) void mma_gemm_f32(const bf16* __restrict__ Ahi,
                                                       const bf16* __restrict__ Alo,
                                                       const bf16* __restrict__ Bhi,
                                                       const bf16* __restrict__ Blo,
                                                       float* __restrict__ C) {
    extern __shared__ __align__(128) char smem[];
    const uint32_t sbase = smem_u32(smem);
    const int tid = threadIdx.x;
    const int n0 = blockIdx.x * BN;
    const int m0 = blockIdx.y * BM;

    float acc[4][4][4];
#pragma unroll
    for (int i = 0; i < 4; i++)
#pragma unroll
        for (int j = 0; j < 4; j++)
#pragma unroll
            for (int e = 0; e < 4; e++) acc[i][j][e] = 0.0f;

    gemm_mainloop(sbase, tid,
                  Ahi + (size_t)m0 * GK, Alo + (size_t)m0 * GK,
                  Bhi + (size_t)n0 * GK, Blo + (size_t)n0 * GK, acc);

    const int lane = tid & 31;
    const int warp = tid >> 5;
    const int warp_m = warp >> 2;
    const int warp_n = warp & 3;
    const int er = lane >> 2;
    const int ec = (lane & 3) * 2;
#pragma unroll
    for (int mt = 0; mt < 4; mt++) {
        const int row = m0 + warp_m * 64 + mt * 16 + er;
#pragma unroll
        for (int nt = 0; nt < 4; nt++) {
            const int col = n0 + warp_n * 32 + nt * 8 + ec;
            *(float2*)&C[(size_t)row * C_DIM + col] = make_float2(acc[mt][nt][0], acc[mt][nt][1]);
            *(float2*)&C[(size_t)(row + 8) * C_DIM + col] = make_float2(acc[mt][nt][2], acc[mt][nt][3]);
        }
    }
}

// ---------------------------------------------------------------------------
// Banded causal attention on tensor cores (bf16 hi/lo, 3-pass) — round-5 version.
// ---------------------------------------------------------------------------
#define AROW 144
#define SROW 200
#define PROWB 400

#define OFF_QH 0
#define OFF_QL 9216
#define OFF_KH 18432
#define OFF_KL 46080
#define OFF_VH 73728
#define OFF_VL 101376
#define OFF_SP 129024
#define ATTN_SMEM 180224

__global__ __launch_bounds__(256, 1) void attn_mma(const bf16* __restrict__ qhi,
                                                   const bf16* __restrict__ qlo,
                                                   const bf16* __restrict__ khi,
                                                   const bf16* __restrict__ klo,
                                                   const bf16* __restrict__ vhi,
                                                   const bf16* __restrict__ vlo,
                                                   bf16* __restrict__ yhi,
                                                   bf16* __restrict__ ylo) {
    extern __shared__ __align__(128) char smem[];
    const uint32_t sbase = smem_u32(smem);
    const int h   = blockIdx.y;
    const int t0  = blockIdx.x * 64;
    const int tid = threadIdx.x;
    const int hoff = h * DHEAD;

    for (int idx = tid; idx < 512; idx += 256) {
        int row = idx >> 3, c = idx & 7;
        size_t src = (size_t)(t0 + row) * C_DIM + hoff + c * 8;
        uint32_t d = row * AROW + c * 16;
        cp16(sbase + OFF_QH + d, qhi + src);
        cp16(sbase + OFF_QL + d, qlo + src);
    }
    for (int idx = tid; idx < 1536; idx += 256) {
        int row = idx >> 3, c = idx & 7;
        int jg = t0 - BANDW + row;
        uint32_t d = row * AROW + c * 16;
        if (jg >= 0) {
            size_t src = (size_t)jg * C_DIM + hoff + c * 8;
            cp16(sbase + OFF_KH + d, khi + src);
            cp16(sbase + OFF_KL + d, klo + src);
            cp16(sbase + OFF_VH + d, vhi + src);
            cp16(sbase + OFF_VL + d, vlo + src);
        } else {
            stz16(sbase + OFF_KH + d);
            stz16(sbase + OFF_KL + d);
            stz16(sbase + OFF_VH + d);
            stz16(sbase + OFF_VL + d);
        }
    }
    cp_commit();
    asm volatile("cp.async.wait_group 0;" ::: "memory");
    __syncthreads();

    const int lane = tid & 31;
    const int warp = tid >> 5;
    const int wm = warp >> 2;
    const int wn = warp & 3;
    const int sel = lane >> 3;
    const int l7  = lane & 7;

    float* Sf = (float*)(smem + OFF_SP);

    // ---- Phase A: S = Q@K^T ----
    {
        const uint32_t aoff = (uint32_t)((wm * 32 + (sel & 1) * 8 + l7) * AROW + (sel >> 1) * 16);
        const uint32_t boff = (uint32_t)((wn * 48 + (sel >> 1) * 8 + l7) * AROW + (sel & 1) * 16);
        const uint32_t sQh = sbase + OFF_QH + aoff, sQl = sbase + OFF_QL + aoff;
        const uint32_t sKh = sbase + OFF_KH + boff, sKl = sbase + OFF_KL + boff;

        float acc[2][6][4];
#pragma unroll
        for (int i = 0; i < 2; i++)
#pragma unroll
            for (int j = 0; j < 6; j++)
#pragma unroll
                for (int e = 0; e < 4; e++) acc[i][j][e] = 0.0f;

#pragma unroll
        for (int ks = 0; ks < 4; ks++) {
            const uint32_t ka = ks * 32;
            uint32_t Ah[2][4], Al[2][4], Bh[6][2], Bl[6][2];
#pragma unroll
            for (int mt = 0; mt < 2; mt++) {
                ldm_x4(Ah[mt], sQh + mt * (16 * AROW) + ka);
                ldm_x4(Al[mt], sQl + mt * (16 * AROW) + ka);
            }
#pragma unroll
            for (int p = 0; p < 3; p++) {
                uint32_t rh[4], rl[4];
                ldm_x4(rh, sKh + p * (16 * AROW) + ka);
                ldm_x4(rl, sKl + p * (16 * AROW) + ka);
                Bh[2 * p][0] = rh[0]; Bh[2 * p][1] = rh[1];
                Bh[2 * p + 1][0] = rh[2]; Bh[2 * p + 1][1] = rh[3];
                Bl[2 * p][0] = rl[0]; Bl[2 * p][1] = rl[1];
                Bl[2 * p + 1][0] = rl[2]; Bl[2 * p + 1][1] = rl[3];
            }
#pragma unroll
            for (int mt = 0; mt < 2; mt++)
#pragma unroll
                for (int nt = 0; nt < 6; nt++) {
                    mma16816(acc[mt][nt], Ah[mt], Bh[nt]);
                    mma16816(acc[mt][nt], Ah[mt], Bl[nt]);
                    mma16816(acc[mt][nt], Al[mt], Bh[nt]);
                }
        }
        const int er = lane >> 2;
        const int ec = (lane & 3) * 2;
#pragma unroll
        for (int mt = 0; mt < 2; mt++) {
            const int row = wm * 32 + mt * 16 + er;
#pragma unroll
            for (int nt = 0; nt < 6; nt++) {
                const int col = wn * 48 + nt * 8 + ec;
                *(float2*)&Sf[row * SROW + col] = make_float2(acc[mt][nt][0], acc[mt][nt][1]);
                *(float2*)&Sf[(row + 8) * SROW + col] = make_float2(acc[mt][nt][2], acc[mt][nt][3]);
            }
        }
    }
    __syncthreads();

    // ---- softmax ----
    {
        const int qi  = tid >> 2;
        const int sub = tid & 3;
        const int i   = t0 + qi;
        const int j0  = sub * 48;
        float s[48];
        const float4* Srow = (const float4*)(Sf + qi * SROW + j0);
#pragma unroll
        for (int n4 = 0; n4 < 12; n4++) {
            float4 v = Srow[n4];
            s[4 * n4] = v.x; s[4 * n4 + 1] = v.y; s[4 * n4 + 2] = v.z; s[4 * n4 + 3] = v.w;
        }
        float mx = -1e30f;
#pragma unroll
        for (int n = 0; n < 48; n++) {
            int jg = t0 - BANDW + j0 + n;
            bool valid = (jg >= 0) && (jg <= i) && ((i - jg) < BANDW);
            s[n] = valid ? s[n] * 0.125f : -1e30f;
            mx = fmaxf(mx, s[n]);
        }
        mx = fmaxf(mx, __shfl_xor_sync(0xFFFFFFFFu, mx, 1));
        mx = fmaxf(mx, __shfl_xor_sync(0xFFFFFFFFu, mx, 2));
        float sum = 0.0f;
#pragma unroll
        for (int n = 0; n < 48; n++) { s[n] = __expf(s[n] - mx); sum += s[n]; }
        sum += __shfl_xor_sync(0xFFFFFFFFu, sum, 1);
        sum += __shfl_xor_sync(0xFFFFFFFFu, sum, 2);
        float inv = 1.0f / sum;

        __syncthreads();

        char* Pb = smem + OFF_SP;
        bf162* PhiRow = (bf162*)(Pb + qi * PROWB + j0 * 2);
        bf162* PloRow = (bf162*)(Pb + 25600 + qi * PROWB + j0 * 2);
#pragma unroll
        for (int n2 = 0; n2 < 24; n2++) {
            float p0 = s[2 * n2] * inv, p1 = s[2 * n2 + 1] * inv;
            bf16 h0, h1, l0, l1;
            split2(p0, h0, l0); split2(p1, h1, l1);
            PhiRow[n2] = bf162(h0, h1);
            PloRow[n2] = bf162(l0, l1);
        }
    }
    __syncthreads();

    // ---- Phase B: O = P@V ----
    {
        const uint32_t aoff = (uint32_t)((wm * 32 + (sel & 1) * 8 + l7) * PROWB + (sel >> 1) * 16);
        const uint32_t voff = (uint32_t)(((sel & 1) * 8 + l7) * AROW + (sel >> 1) * 16 + wn * 32);
        const uint32_t sPh = sbase + OFF_SP + aoff;
        const uint32_t sPl = sbase + OFF_SP + 25600 + aoff;
        const uint32_t sVh = sbase + OFF_VH + voff;
        const uint32_t sVl = sbase + OFF_VL + voff;

        float acc[2][2][4];
#pragma unroll
        for (int i = 0; i < 2; i++)
#pragma unroll
            for (int j = 0; j < 2; j++)
#pragma unroll
                for (int e = 0; e < 4; e++) acc[i][j][e] = 0.0f;

#pragma unroll
        for (int ks = 0; ks < 12; ks++) {
            uint32_t Ph[2][4], Pl[2][4], Vh[2][2], Vl[2][2];
#pragma unroll
            for (int mt = 0; mt < 2; mt++) {
                ldm_x4(Ph[mt], sPh + mt * (16 * PROWB) + ks * 32);
                ldm_x4(Pl[mt], sPl + mt * (16 * PROWB) + ks * 32);
            }
            {
                uint32_t rh[4], rl[4];
                ldm_x4t(rh, sVh + ks * (16 * AROW));
                ldm_x4t(rl, sVl + ks * (16 * AROW));
                Vh[0][0] = rh[0]; Vh[0][1] = rh[1]; Vh[1][0] = rh[2]; Vh[1][1] = rh[3];
                Vl[0][0] = rl[0]; Vl[0][1] = rl[1]; Vl[1][0] = rl[2]; Vl[1][1] = rl[3];
            }
#pragma unroll
            for (int mt = 0; mt < 2; mt++)
#pragma unroll
                for (int nt = 0; nt < 2; nt++) {
                    mma16816(acc[mt][nt], Ph[mt], Vh[nt]);
                    mma16816(acc[mt][nt], Ph[mt], Vl[nt]);
                    mma16816(acc[mt][nt], Pl[mt], Vh[nt]);
                }
        }

        const int er = lane >> 2;
        const int ec = (lane & 3) * 2;
#pragma unroll
        for (int mt = 0; mt < 2; mt++) {
            const int row = wm * 32 + mt * 16 + er;
#pragma unroll
            for (int nt = 0; nt < 2; nt++) {
                const int col = wn * 16 + nt * 8 + ec;
#pragma unroll
                for (int hh = 0; hh < 2; hh++) {
                    float c0 = acc[mt][nt][2 * hh], c1 = acc[mt][nt][2 * hh + 1];
                    bf16 h0, h1, l0, l1;
                    split2(c0, h0, l0); split2(c1, h1, l1);
                    size_t off = (size_t)(t0 + row + 8 * hh) * C_DIM + hoff + col;
                    *(bf162*)&yhi[off] = bf162(h0, h1);
                    *(bf162*)&ylo[off] = bf162(l0, l1);
                }
            }
        }
    }
}

// ---------------------------------------------------------------------------
extern "C" void kernel_launch(void* const* d_in, const int* in_sizes, int n_in,
                              void* d_out, int out_size) {
    const float* x  = (const float*)d_in[0];
    const float* Wq = (const float*)d_in[1];
    const float* Wk = (const float*)d_in[2];
    const float* Wv = (const float*)d_in[3];
    const float* Wo = (const float*)d_in[4];
    float* out = (float*)d_out;

    bf16 *xhi, *xlo, *qhi, *qlo, *khi, *klo, *vhi, *vlo, *ahi, *alo, *whi, *wlo;
    cudaGetSymbolAddress((void**)&xhi, g_xhi);
    cudaGetSymbolAddress((void**)&xlo, g_xlo);
    cudaGetSymbolAddress((void**)&qhi, g_qhi);
    cudaGetSymbolAddress((void**)&qlo, g_qlo);
    cudaGetSymbolAddress((void**)&khi, g_khi);
    cudaGetSymbolAddress((void**)&klo, g_klo);
    cudaGetSymbolAddress((void**)&vhi, g_vhi);
    cudaGetSymbolAddress((void**)&vlo, g_vlo);
    cudaGetSymbolAddress((void**)&ahi, g_ahi);
    cudaGetSymbolAddress((void**)&alo, g_alo);
    cudaGetSymbolAddress((void**)&whi, g_whi);
    cudaGetSymbolAddress((void**)&wlo, g_wlo);

    cudaFuncSetAttribute(mma_gemm_qkv, cudaFuncAttributeMaxDynamicSharedMemorySize, GEMM_SMEM);
    cudaFuncSetAttribute(mma_gemm_f32, cudaFuncAttributeMaxDynamicSharedMemorySize, GEMM_SMEM);
    cudaFuncSetAttribute(attn_mma, cudaFuncAttributeMaxDynamicSharedMemorySize, ATTN_SMEM);

    const int NX4 = T_SEQ * C_DIM / 4;
    const int NW4 = C_DIM * C_DIM / 4;
    const size_t WSZ = (size_t)C_DIM * C_DIM;

    split_kernel<<<(NX4 + 255) / 256, 256>>>(x, xhi, xlo, NX4);
    split_w4_kernel<<<dim3((NW4 + 255) / 256, 4), 256>>>(Wq, Wk, Wv, Wo, whi, wlo, NW4);

    mma_gemm_qkv<<<dim3(24, 32), 256, GEMM_SMEM>>>(xhi, xlo, whi, wlo,
                                                   qhi, qlo, khi, klo, vhi, vlo);

    attn_mma<<<dim3(T_SEQ / 64, NH), 256, ATTN_SMEM>>>(qhi, qlo, khi, klo, vhi, vlo, ahi, alo);

    mma_gemm_f32<<<dim3(8, 32), 256, GEMM_SMEM>>>(ahi, alo, whi + 3 * WSZ, wlo + 3 * WSZ, out);
}

// round 7
// speedup vs baseline: 1.4138x; 1.4138x over previous
#include <cuda_runtime.h>
#include <cuda_fp16.h>
#include <cstdint>

#define T_SEQ 4096
#define C_DIM 1024
#define NH    16
#define DHEAD 64
#define BANDW 128

// ---------------------------------------------------------------------------
// Scratch (__device__ globals; allocation-free rule)
// ---------------------------------------------------------------------------
__device__ __half g_xhi[T_SEQ * C_DIM];
__device__ __half g_xlo[T_SEQ * C_DIM];
__device__ __half g_qhi[T_SEQ * C_DIM];
__device__ __half g_qlo[T_SEQ * C_DIM];
__device__ __half g_k[T_SEQ * C_DIM];
__device__ __half g_v[T_SEQ * C_DIM];
__device__ __half g_ahi[T_SEQ * C_DIM];
__device__ __half g_alo[T_SEQ * C_DIM];
__device__ __half g_w[4][C_DIM * C_DIM];

// ---------------------------------------------------------------------------
// PTX helpers (base features only — compute_103 PTX target)
// ---------------------------------------------------------------------------
__device__ __forceinline__ uint32_t smem_u32(const void* p) {
    uint32_t a;
    asm("{ .reg .u64 t; cvta.to.shared.u64 t, %1; cvt.u32.u64 %0, t; }" : "=r"(a) : "l"(p));
    return a;
}
__device__ __forceinline__ void cp16(uint32_t dst, const void* src) {
    asm volatile("cp.async.cg.shared.global [%0], [%1], 16;" :: "r"(dst), "l"(src));
}
__device__ __forceinline__ void cp_commit() {
    asm volatile("cp.async.commit_group;" ::: "memory");
}
__device__ __forceinline__ void stz16(uint32_t a) {
    asm volatile("st.shared.v4.u32 [%0], {%1,%1,%1,%1};" :: "r"(a), "r"(0) : "memory");
}
__device__ __forceinline__ void ldm_x4(uint32_t* r, uint32_t a) {
    asm volatile("ldmatrix.sync.aligned.m8n8.x4.shared.b16 {%0,%1,%2,%3}, [%4];"
                 : "=r"(r[0]), "=r"(r[1]), "=r"(r[2]), "=r"(r[3]) : "r"(a));
}
__device__ __forceinline__ void ldm_x4t(uint32_t* r, uint32_t a) {
    asm volatile("ldmatrix.sync.aligned.m8n8.x4.trans.shared.b16 {%0,%1,%2,%3}, [%4];"
                 : "=r"(r[0]), "=r"(r[1]), "=r"(r[2]), "=r"(r[3]) : "r"(a));
}
__device__ __forceinline__ void mma16816h(float* d, const uint32_t* a, const uint32_t* b) {
    asm volatile("mma.sync.aligned.m16n8k16.row.col.f32.f16.f16.f32 "
                 "{%0,%1,%2,%3}, {%4,%5,%6,%7}, {%8,%9}, {%0,%1,%2,%3};"
                 : "+f"(d[0]), "+f"(d[1]), "+f"(d[2]), "+f"(d[3])
                 : "r"(a[0]), "r"(a[1]), "r"(a[2]), "r"(a[3]), "r"(b[0]), "r"(b[1]));
}
__device__ __forceinline__ void split2h(float x, __half& h, __half& l) {
    h = __float2half_rn(x);
    l = __float2half_rn(x - __half2float(h));
}

// ---------------------------------------------------------------------------
// fp32 -> (hi, lo) fp16 split / fp32 -> fp16 weight convert
// ---------------------------------------------------------------------------
__global__ __launch_bounds__(256) void split_kernel(const float* __restrict__ in,
                                                    __half* __restrict__ hi,
                                                    __half* __restrict__ lo, int n4) {
    int i = blockIdx.x * 256 + threadIdx.x;
    if (i >= n4) return;
    float4 v = ((const float4*)in)[i];
    __half h0, h1, h2, h3, l0, l1, l2, l3;
    split2h(v.x, h0, l0); split2h(v.y, h1, l1); split2h(v.z, h2, l2); split2h(v.w, h3, l3);
    __half2* hp = (__half2*)(hi + 4 * (size_t)i);
    __half2* lp = (__half2*)(lo + 4 * (size_t)i);
    hp[0] = __halves2half2(h0, h1); hp[1] = __halves2half2(h2, h3);
    lp[0] = __halves2half2(l0, l1); lp[1] = __halves2half2(l2, l3);
}

__global__ __launch_bounds__(256) void conv_w4_kernel(const float* __restrict__ w0,
                                                      const float* __restrict__ w1,
                                                      const float* __restrict__ w2,
                                                      const float* __restrict__ w3,
                                                      __half* __restrict__ w, int n4) {
    int i = blockIdx.x * 256 + threadIdx.x;
    if (i >= n4) return;
    int wsel = blockIdx.y;
    const float* in = (wsel == 0) ? w0 : (wsel == 1) ? w1 : (wsel == 2) ? w2 : w3;
    size_t base = (size_t)wsel * (C_DIM * C_DIM);
    float4 v = ((const float4*)in)[i];
    __half2* hp = (__half2*)(w + base + 4 * (size_t)i);
    hp[0] = __floats2half2_rn(v.x, v.y);
    hp[1] = __floats2half2_rn(v.z, v.w);
}

// ---------------------------------------------------------------------------
// Shared GEMM mainloop (fp16, A hi/lo 2-pass): 128x128 CTA tile, BK=16,
// 256 threads = 2x4 warps (warp tile 64x32), 4-stage cp.async ring,
// 48B padded rows, 73.7KB smem -> 2 CTAs/SM.
// ---------------------------------------------------------------------------
#define BM 128
#define BN 128
#define BK 16
#define GK C_DIM
#define NCHUNK (GK / BK)          // 64
#define ROWB 48
#define TILEB (128 * ROWB)        // 6144 B
#define STAGEB (3 * TILEB)        // 18432 B
#define NSTAGE 4
#define GEMM_SMEM (NSTAGE * STAGEB)   // 73728 B

__device__ __forceinline__ void gemm_mainloop(uint32_t sbase, int tid,
                                              const __half* __restrict__ tA_hi,
                                              const __half* __restrict__ tA_lo,
                                              const __half* __restrict__ tB,
                                              float (&acc)[4][4][4]) {
    const int lane = tid & 31;
    const int warp = tid >> 5;
    const int warp_m = warp >> 2;
    const int warp_n = warp & 3;
    const int r0 = tid >> 1;           // 0..127
    const int q  = tid & 1;
    const __half* tb[3] = {tA_hi, tA_lo, tB};

    auto load_stage = [&](int s, int c) {
        const int k0 = c * BK;
        const uint32_t ds = sbase + s * STAGEB;
#pragma unroll
        for (int t = 0; t < 3; t++)
            cp16(ds + t * TILEB + r0 * ROWB + q * 16,
                 tb[t] + (size_t)r0 * GK + k0 + q * 8);
        cp_commit();
    };

    const int sel = lane >> 3;
    const int l7  = lane & 7;
    const uint32_t aoff = (uint32_t)((warp_m * 64 + (sel & 1) * 8 + l7) * ROWB + (sel >> 1) * 16);
    const uint32_t boff = (uint32_t)((warp_n * 32 + (sel >> 1) * 8 + l7) * ROWB + (sel & 1) * 16);

    load_stage(0, 0);
    load_stage(1, 1);
    load_stage(2, 2);

    for (int c = 0; c < NCHUNK; c++) {
        const int pend = NCHUNK - 1 - c;
        if (pend >= 2)      asm volatile("cp.async.wait_group 2;" ::: "memory");
        else if (pend == 1) asm volatile("cp.async.wait_group 1;" ::: "memory");
        else                asm volatile("cp.async.wait_group 0;" ::: "memory");
        __syncthreads();

        if (c + 3 < NCHUNK) load_stage((c + 3) & 3, c + 3);

        const uint32_t ds = sbase + (c & 3) * STAGEB;
        const uint32_t sAh = ds + 0 * TILEB + aoff;
        const uint32_t sAl = ds + 1 * TILEB + aoff;
        const uint32_t sB  = ds + 2 * TILEB + boff;

        uint32_t Ah[4][4], Al[4][4], Bv[4][2];
#pragma unroll
        for (int mt = 0; mt < 4; mt++) {
            ldm_x4(Ah[mt], sAh + mt * (16 * ROWB));
            ldm_x4(Al[mt], sAl + mt * (16 * ROWB));
        }
#pragma unroll
        for (int p = 0; p < 2; p++) {
            uint32_t rb[4];
            ldm_x4(rb, sB + p * (16 * ROWB));
            Bv[2 * p][0] = rb[0]; Bv[2 * p][1] = rb[1];
            Bv[2 * p + 1][0] = rb[2]; Bv[2 * p + 1][1] = rb[3];
        }
#pragma unroll
        for (int mt = 0; mt < 4; mt++)
#pragma unroll
            for (int nt = 0; nt < 4; nt++)
                mma16816h(acc[mt][nt], Ah[mt], Bv[nt]);
#pragma unroll
        for (int mt = 0; mt < 4; mt++)
#pragma unroll
            for (int nt = 0; nt < 4; nt++)
                mma16816h(acc[mt][nt], Al[mt], Bv[nt]);
    }
}

// ---- Fused QKV projection: Q -> hi/lo, K/V -> single fp16 ----
__global__ __launch_bounds__(256, 2) void mma_gemm_qkv(const __half* __restrict__ xhi,
                                                       const __half* __restrict__ xlo,
                                                       const __half* __restrict__ w,
                                                       __half* __restrict__ qhi,
                                                       __half* __restrict__ qlo,
                                                       __half* __restrict__ kk,
                                                       __half* __restrict__ vv) {
    extern __shared__ __align__(128) char smem[];
    const uint32_t sbase = smem_u32(smem);
    const int tid = threadIdx.x;
    const int which = blockIdx.x >> 3;
    const int n0 = (blockIdx.x & 7) * BN;
    const int m0 = blockIdx.y * BM;
    const size_t WSZ = (size_t)C_DIM * C_DIM;

    float acc[4][4][4];
#pragma unroll
    for (int i = 0; i < 4; i++)
#pragma unroll
        for (int j = 0; j < 4; j++)
#pragma unroll
            for (int e = 0; e < 4; e++) acc[i][j][e] = 0.0f;

    gemm_mainloop(sbase, tid,
                  xhi + (size_t)m0 * GK, xlo + (size_t)m0 * GK,
                  w + which * WSZ + (size_t)n0 * GK, acc);

    const int lane = tid & 31;
    const int warp = tid >> 5;
    const int warp_m = warp >> 2;
    const int warp_n = warp & 3;
    const int er = lane >> 2;
    const int ec = (lane & 3) * 2;

    if (which == 0) {
#pragma unroll
        for (int mt = 0; mt < 4; mt++) {
            const int row = m0 + warp_m * 64 + mt * 16 + er;
#pragma unroll
            for (int nt = 0; nt < 4; nt++) {
                const int col = n0 + warp_n * 32 + nt * 8 + ec;
#pragma unroll
                for (int hh = 0; hh < 2; hh++) {
                    float c0 = acc[mt][nt][2 * hh], c1 = acc[mt][nt][2 * hh + 1];
                    __half h0, h1, l0, l1;
                    split2h(c0, h0, l0); split2h(c1, h1, l1);
                    size_t off = (size_t)(row + 8 * hh) * C_DIM + col;
                    *(__half2*)&qhi[off] = __halves2half2(h0, h1);
                    *(__half2*)&qlo[off] = __halves2half2(l0, l1);
                }
            }
        }
    } else {
        __half* o = (which == 1) ? kk : vv;
#pragma unroll
        for (int mt = 0; mt < 4; mt++) {
            const int row = m0 + warp_m * 64 + mt * 16 + er;
#pragma unroll
            for (int nt = 0; nt < 4; nt++) {
                const int col = n0 + warp_n * 32 + nt * 8 + ec;
#pragma unroll
                for (int hh = 0; hh < 2; hh++) {
                    size_t off = (size_t)(row + 8 * hh) * C_DIM + col;
                    *(__half2*)&o[off] =
                        __floats2half2_rn(acc[mt][nt][2 * hh], acc[mt][nt][2 * hh + 1]);
                }
            }
        }
    }
}

// ---- Output projection: fp32 epilogue ----
__global__ __launch_bounds__(256, 2) void mma_gemm_f32(const __half* __restrict__ Ahi,
                                                       const __half* __restrict__ Alo,
                                                       const __half* __restrict__ B,
                                                       float* __restrict__ C) {
    extern __shared__ __align__(128) char smem[];
    const uint32_t sbase = smem_u32(smem);
    const int tid = threadIdx.x;
    const int n0 = blockIdx.x * BN;
    const int m0 = blockIdx.y * BM;

    float acc[4][4][4];
#pragma unroll
    for (int i = 0; i < 4; i++)
#pragma unroll
        for (int j = 0; j < 4; j++)
#pragma unroll
            for (int e = 0; e < 4; e++) acc[i][j][e] = 0.0f;

    gemm_mainloop(sbase, tid,
                  Ahi + (size_t)m0 * GK, Alo + (size_t)m0 * GK,
                  B + (size_t)n0 * GK, acc);

    const int lane = tid & 31;
    const int warp = tid >> 5;
    const int warp_m = warp >> 2;
    const int warp_n = warp & 3;
    const int er = lane >> 2;
    const int ec = (lane & 3) * 2;
#pragma unroll
    for (int mt = 0; mt < 4; mt++) {
        const int row = m0 + warp_m * 64 + mt * 16 + er;
#pragma unroll
        for (int nt = 0; nt < 4; nt++) {
            const int col = n0 + warp_n * 32 + nt * 8 + ec;
            *(float2*)&C[(size_t)row * C_DIM + col] = make_float2(acc[mt][nt][0], acc[mt][nt][1]);
            *(float2*)&C[(size_t)(row + 8) * C_DIM + col] = make_float2(acc[mt][nt][2], acc[mt][nt][3]);
        }
    }
}

// ---------------------------------------------------------------------------
// Banded causal attention on tensor cores (fp16, 2-pass).
// Block = (head, 64-query tile), 256 threads (2x4 warps).
// Phase A: S = Qhi@K^T + Qlo@K^T   (M=64, N=192, K=64), warp tile 32x48.
// Softmax fp32 in smem; P -> fp16 hi/lo (overlaying S region).
// Phase B: O = Phi@V + Plo@V       (M=64, N=64, K=192), V via ldmatrix.trans.
// ---------------------------------------------------------------------------
#define AROW 144
#define SROW 200
#define PROWB 400

#define OFF_QH 0
#define OFF_QL 9216
#define OFF_K  18432
#define OFF_V  46080
#define OFF_SP 73728
#define ATTN_SMEM 124928

__global__ __launch_bounds__(256, 1) void attn_mma(const __half* __restrict__ qhi,
                                                   const __half* __restrict__ qlo,
                                                   const __half* __restrict__ kk,
                                                   const __half* __restrict__ vv,
                                                   __half* __restrict__ yhi,
                                                   __half* __restrict__ ylo) {
    extern __shared__ __align__(128) char smem[];
    const uint32_t sbase = smem_u32(smem);
    const int h   = blockIdx.y;
    const int t0  = blockIdx.x * 64;
    const int tid = threadIdx.x;
    const int hoff = h * DHEAD;

    for (int idx = tid; idx < 512; idx += 256) {
        int row = idx >> 3, c = idx & 7;
        size_t src = (size_t)(t0 + row) * C_DIM + hoff + c * 8;
        uint32_t d = row * AROW + c * 16;
        cp16(sbase + OFF_QH + d, qhi + src);
        cp16(sbase + OFF_QL + d, qlo + src);
    }
    for (int idx = tid; idx < 1536; idx += 256) {
        int row = idx >> 3, c = idx & 7;
        int jg = t0 - BANDW + row;
        uint32_t d = row * AROW + c * 16;
        if (jg >= 0) {
            size_t src = (size_t)jg * C_DIM + hoff + c * 8;
            cp16(sbase + OFF_K + d, kk + src);
            cp16(sbase + OFF_V + d, vv + src);
        } else {
            stz16(sbase + OFF_K + d);
            stz16(sbase + OFF_V + d);
        }
    }
    cp_commit();
    asm volatile("cp.async.wait_group 0;" ::: "memory");
    __syncthreads();

    const int lane = tid & 31;
    const int warp = tid >> 5;
    const int wm = warp >> 2;
    const int wn = warp & 3;
    const int sel = lane >> 3;
    const int l7  = lane & 7;

    float* Sf = (float*)(smem + OFF_SP);

    // ---- Phase A: S = Q@K^T (2-pass) ----
    {
        const uint32_t aoff = (uint32_t)((wm * 32 + (sel & 1) * 8 + l7) * AROW + (sel >> 1) * 16);
        const uint32_t boff = (uint32_t)((wn * 48 + (sel >> 1) * 8 + l7) * AROW + (sel & 1) * 16);
        const uint32_t sQh = sbase + OFF_QH + aoff, sQl = sbase + OFF_QL + aoff;
        const uint32_t sK  = sbase + OFF_K + boff;

        float acc[2][6][4];
#pragma unroll
        for (int i = 0; i < 2; i++)
#pragma unroll
            for (int j = 0; j < 6; j++)
#pragma unroll
                for (int e = 0; e < 4; e++) acc[i][j][e] = 0.0f;

#pragma unroll
        for (int ks = 0; ks < 4; ks++) {
            const uint32_t ka = ks * 32;
            uint32_t Ah[2][4], Al[2][4], Kv[6][2];
#pragma unroll
            for (int mt = 0; mt < 2; mt++) {
                ldm_x4(Ah[mt], sQh + mt * (16 * AROW) + ka);
                ldm_x4(Al[mt], sQl + mt * (16 * AROW) + ka);
            }
#pragma unroll
            for (int p = 0; p < 3; p++) {
                uint32_t rb[4];
                ldm_x4(rb, sK + p * (16 * AROW) + ka);
                Kv[2 * p][0] = rb[0]; Kv[2 * p][1] = rb[1];
                Kv[2 * p + 1][0] = rb[2]; Kv[2 * p + 1][1] = rb[3];
            }
#pragma unroll
            for (int mt = 0; mt < 2; mt++)
#pragma unroll
                for (int nt = 0; nt < 6; nt++) {
                    mma16816h(acc[mt][nt], Ah[mt], Kv[nt]);
                    mma16816h(acc[mt][nt], Al[mt], Kv[nt]);
                }
        }
        const int er = lane >> 2;
        const int ec = (lane & 3) * 2;
#pragma unroll
        for (int mt = 0; mt < 2; mt++) {
            const int row = wm * 32 + mt * 16 + er;
#pragma unroll
            for (int nt = 0; nt < 6; nt++) {
                const int col = wn * 48 + nt * 8 + ec;
                *(float2*)&Sf[row * SROW + col] = make_float2(acc[mt][nt][0], acc[mt][nt][1]);
                *(float2*)&Sf[(row + 8) * SROW + col] = make_float2(acc[mt][nt][2], acc[mt][nt][3]);
            }
        }
    }
    __syncthreads();

    // ---- softmax ----
    {
        const int qi  = tid >> 2;
        const int sub = tid & 3;
        const int i   = t0 + qi;
        const int j0  = sub * 48;
        float s[48];
        const float4* Srow = (const float4*)(Sf + qi * SROW + j0);
#pragma unroll
        for (int n4 = 0; n4 < 12; n4++) {
            float4 v = Srow[n4];
            s[4 * n4] = v.x; s[4 * n4 + 1] = v.y; s[4 * n4 + 2] = v.z; s[4 * n4 + 3] = v.w;
        }
        float mx = -1e30f;
#pragma unroll
        for (int n = 0; n < 48; n++) {
            int jg = t0 - BANDW + j0 + n;
            bool valid = (jg >= 0) && (jg <= i) && ((i - jg) < BANDW);
            s[n] = valid ? s[n] * 0.125f : -1e30f;
            mx = fmaxf(mx, s[n]);
        }
        mx = fmaxf(mx, __shfl_xor_sync(0xFFFFFFFFu, mx, 1));
        mx = fmaxf(mx, __shfl_xor_sync(0xFFFFFFFFu, mx, 2));
        float sum = 0.0f;
#pragma unroll
        for (int n = 0; n < 48; n++) { s[n] = __expf(s[n] - mx); sum += s[n]; }
        sum += __shfl_xor_sync(0xFFFFFFFFu, sum, 1);
        sum += __shfl_xor_sync(0xFFFFFFFFu, sum, 2);
        float inv = 1.0f / sum;

        __syncthreads();

        char* Pb = smem + OFF_SP;
        __half2* PhiRow = (__half2*)(Pb + qi * PROWB + j0 * 2);
        __half2* PloRow = (__half2*)(Pb + 25600 + qi * PROWB + j0 * 2);
#pragma unroll
        for (int n2 = 0; n2 < 24; n2++) {
            float p0 = s[2 * n2] * inv, p1 = s[2 * n2 + 1] * inv;
            __half h0, h1, l0, l1;
            split2h(p0, h0, l0); split2h(p1, h1, l1);
            PhiRow[n2] = __halves2half2(h0, h1);
            PloRow[n2] = __halves2half2(l0, l1);
        }
    }
    __syncthreads();

    // ---- Phase B: O = P@V (2-pass) ----
    {
        const uint32_t aoff = (uint32_t)((wm * 32 + (sel & 1) * 8 + l7) * PROWB + (sel >> 1) * 16);
        const uint32_t voff = (uint32_t)(((sel & 1) * 8 + l7) * AROW + (sel >> 1) * 16 + wn * 32);
        const uint32_t sPh = sbase + OFF_SP + aoff;
        const uint32_t sPl = sbase + OFF_SP + 25600 + aoff;
        const uint32_t sV  = sbase + OFF_V + voff;

        float acc[2][2][4];
#pragma unroll
        for (int i = 0; i < 2; i++)
#pragma unroll
            for (int j = 0; j < 2; j++)
#pragma unroll
                for (int e = 0; e < 4; e++) acc[i][j][e] = 0.0f;

#pragma unroll
        for (int ks = 0; ks < 12; ks++) {
            uint32_t Ph[2][4], Pl[2][4], Vv[2][2];
#pragma unroll
            for (int mt = 0; mt < 2; mt++) {
                ldm_x4(Ph[mt], sPh + mt * (16 * PROWB) + ks * 32);
                ldm_x4(Pl[mt], sPl + mt * (16 * PROWB) + ks * 32);
            }
            {
                uint32_t rb[4];
                ldm_x4t(rb, sV + ks * (16 * AROW));
                Vv[0][0] = rb[0]; Vv[0][1] = rb[1]; Vv[1][0] = rb[2]; Vv[1][1] = rb[3];
            }
#pragma unroll
            for (int mt = 0; mt < 2; mt++)
#pragma unroll
                for (int nt = 0; nt < 2; nt++) {
                    mma16816h(acc[mt][nt], Ph[mt], Vv[nt]);
                    mma16816h(acc[mt][nt], Pl[mt], Vv[nt]);
                }
        }

        const int er = lane >> 2;
        const int ec = (lane & 3) * 2;
#pragma unroll
        for (int mt = 0; mt < 2; mt++) {
            const int row = wm * 32 + mt * 16 + er;
#pragma unroll
            for (int nt = 0; nt < 2; nt++) {
                const int col = wn * 16 + nt * 8 + ec;
#pragma unroll
                for (int hh = 0; hh < 2; hh++) {
                    float c0 = acc[mt][nt][2 * hh], c1 = acc[mt][nt][2 * hh + 1];
                    __half h0, h1, l0, l1;
                    split2h(c0, h0, l0); split2h(c1, h1, l1);
                    size_t off = (size_t)(t0 + row + 8 * hh) * C_DIM + hoff + col;
                    *(__half2*)&yhi[off] = __halves2half2(h0, h1);
                    *(__half2*)&ylo[off] = __halves2half2(l0, l1);
                }
            }
        }
    }
}

// ---------------------------------------------------------------------------
extern "C" void kernel_launch(void* const* d_in, const int* in_sizes, int n_in,
                              void* d_out, int out_size) {
    const float* x  = (const float*)d_in[0];
    const float* Wq = (const float*)d_in[1];
    const float* Wk = (const float*)d_in[2];
    const float* Wv = (const float*)d_in[3];
    const float* Wo = (const float*)d_in[4];
    float* out = (float*)d_out;

    __half *xhi, *xlo, *qhi, *qlo, *kk, *vv, *ahi, *alo, *w;
    cudaGetSymbolAddress((void**)&xhi, g_xhi);
    cudaGetSymbolAddress((void**)&xlo, g_xlo);
    cudaGetSymbolAddress((void**)&qhi, g_qhi);
    cudaGetSymbolAddress((void**)&qlo, g_qlo);
    cudaGetSymbolAddress((void**)&kk, g_k);
    cudaGetSymbolAddress((void**)&vv, g_v);
    cudaGetSymbolAddress((void**)&ahi, g_ahi);
    cudaGetSymbolAddress((void**)&alo, g_alo);
    cudaGetSymbolAddress((void**)&w, g_w);

    cudaFuncSetAttribute(mma_gemm_qkv, cudaFuncAttributeMaxDynamicSharedMemorySize, GEMM_SMEM);
    cudaFuncSetAttribute(mma_gemm_f32, cudaFuncAttributeMaxDynamicSharedMemorySize, GEMM_SMEM);
    cudaFuncSetAttribute(attn_mma, cudaFuncAttributeMaxDynamicSharedMemorySize, ATTN_SMEM);

    const int NX4 = T_SEQ * C_DIM / 4;
    const int NW4 = C_DIM * C_DIM / 4;
    const size_t WSZ = (size_t)C_DIM * C_DIM;

    split_kernel<<<(NX4 + 255) / 256, 256>>>(x, xhi, xlo, NX4);
    conv_w4_kernel<<<dim3((NW4 + 255) / 256, 4), 256>>>(Wq, Wk, Wv, Wo, w, NW4);

    mma_gemm_qkv<<<dim3(24, 32), 256, GEMM_SMEM>>>(xhi, xlo, w, qhi, qlo, kk, vv);

    attn_mma<<<dim3(T_SEQ / 64, NH), 256, ATTN_SMEM>>>(qhi, qlo, kk, vv, ahi, alo);

    mma_gemm_f32<<<dim3(8, 32), 256, GEMM_SMEM>>>(ahi, alo, w + 3 * WSZ, out);
}

// round 8
// speedup vs baseline: 2.5116x; 1.7765x over previous
#include <cuda_runtime.h>
#include <cuda_fp16.h>
#include <cstdint>

#define T_SEQ 4096
#define C_DIM 1024
#define NH    16
#define DHEAD 64
#define BANDW 128

// ---------------------------------------------------------------------------
// Scratch (__device__ globals; allocation-free rule)
// ---------------------------------------------------------------------------
__device__ __half g_x[T_SEQ * C_DIM];
__device__ __half g_q[T_SEQ * C_DIM];
__device__ __half g_k[T_SEQ * C_DIM];
__device__ __half g_v[T_SEQ * C_DIM];
__device__ __half g_a[T_SEQ * C_DIM];
__device__ __half g_w[4][C_DIM * C_DIM];

// ---------------------------------------------------------------------------
// PTX helpers (base features only — compute_103 PTX target)
// ---------------------------------------------------------------------------
__device__ __forceinline__ uint32_t smem_u32(const void* p) {
    uint32_t a;
    asm("{ .reg .u64 t; cvta.to.shared.u64 t, %1; cvt.u32.u64 %0, t; }" : "=r"(a) : "l"(p));
    return a;
}
__device__ __forceinline__ void cp16(uint32_t dst, const void* src) {
    asm volatile("cp.async.cg.shared.global [%0], [%1], 16;" :: "r"(dst), "l"(src));
}
__device__ __forceinline__ void cp_commit() {
    asm volatile("cp.async.commit_group;" ::: "memory");
}
__device__ __forceinline__ void stz16(uint32_t a) {
    asm volatile("st.shared.v4.u32 [%0], {%1,%1,%1,%1};" :: "r"(a), "r"(0) : "memory");
}
__device__ __forceinline__ void ldm_x4(uint32_t* r, uint32_t a) {
    asm volatile("ldmatrix.sync.aligned.m8n8.x4.shared.b16 {%0,%1,%2,%3}, [%4];"
                 : "=r"(r[0]), "=r"(r[1]), "=r"(r[2]), "=r"(r[3]) : "r"(a));
}
__device__ __forceinline__ void ldm_x4t(uint32_t* r, uint32_t a) {
    asm volatile("ldmatrix.sync.aligned.m8n8.x4.trans.shared.b16 {%0,%1,%2,%3}, [%4];"
                 : "=r"(r[0]), "=r"(r[1]), "=r"(r[2]), "=r"(r[3]) : "r"(a));
}
__device__ __forceinline__ void mma16816h(float* d, const uint32_t* a, const uint32_t* b) {
    asm volatile("mma.sync.aligned.m16n8k16.row.col.f32.f16.f16.f32 "
                 "{%0,%1,%2,%3}, {%4,%5,%6,%7}, {%8,%9}, {%0,%1,%2,%3};"
                 : "+f"(d[0]), "+f"(d[1]), "+f"(d[2]), "+f"(d[3])
                 : "r"(a[0]), "r"(a[1]), "r"(a[2]), "r"(a[3]), "r"(b[0]), "r"(b[1]));
}

// ---------------------------------------------------------------------------
// fp32 -> fp16 converts
// ---------------------------------------------------------------------------
__global__ __launch_bounds__(256) void conv_x_kernel(const float* __restrict__ in,
                                                     __half* __restrict__ o, int n4) {
    int i = blockIdx.x * 256 + threadIdx.x;
    if (i >= n4) return;
    float4 v = ((const float4*)in)[i];
    __half2* hp = (__half2*)(o + 4 * (size_t)i);
    hp[0] = __floats2half2_rn(v.x, v.y);
    hp[1] = __floats2half2_rn(v.z, v.w);
}

__global__ __launch_bounds__(256) void conv_w4_kernel(const float* __restrict__ w0,
                                                      const float* __restrict__ w1,
                                                      const float* __restrict__ w2,
                                                      const float* __restrict__ w3,
                                                      __half* __restrict__ w, int n4) {
    int i = blockIdx.x * 256 + threadIdx.x;
    if (i >= n4) return;
    int wsel = blockIdx.y;
    const float* in = (wsel == 0) ? w0 : (wsel == 1) ? w1 : (wsel == 2) ? w2 : w3;
    size_t base = (size_t)wsel * (C_DIM * C_DIM);
    float4 v = ((const float4*)in)[i];
    __half2* hp = (__half2*)(w + base + 4 * (size_t)i);
    hp[0] = __floats2half2_rn(v.x, v.y);
    hp[1] = __floats2half2_rn(v.z, v.w);
}

// ---------------------------------------------------------------------------
// Shared GEMM mainloop (fp16 single-pass): 128x128 CTA tile, BK=16,
// 256 threads = 2x4 warps (warp tile 64x32), 4-stage cp.async ring,
// 48B padded rows, 49.2KB smem -> 2 CTAs/SM.
// ---------------------------------------------------------------------------
#define BM 128
#define BN 128
#define BK 16
#define GK C_DIM
#define NCHUNK (GK / BK)          // 64
#define ROWB 48
#define TILEB (128 * ROWB)        // 6144 B
#define STAGEB (2 * TILEB)        // 12288 B
#define NSTAGE 4
#define GEMM_SMEM (NSTAGE * STAGEB)   // 49152 B

__device__ __forceinline__ void gemm_mainloop(uint32_t sbase, int tid,
                                              const __half* __restrict__ tA,
                                              const __half* __restrict__ tB,
                                              float (&acc)[4][4][4]) {
    const int lane = tid & 31;
    const int warp = tid >> 5;
    const int warp_m = warp >> 2;
    const int warp_n = warp & 3;
    const int r0 = tid >> 1;           // 0..127
    const int q  = tid & 1;
    const __half* tb[2] = {tA, tB};

    auto load_stage = [&](int s, int c) {
        const int k0 = c * BK;
        const uint32_t ds = sbase + s * STAGEB;
#pragma unroll
        for (int t = 0; t < 2; t++)
            cp16(ds + t * TILEB + r0 * ROWB + q * 16,
                 tb[t] + (size_t)r0 * GK + k0 + q * 8);
        cp_commit();
    };

    const int sel = lane >> 3;
    const int l7  = lane & 7;
    const uint32_t aoff = (uint32_t)((warp_m * 64 + (sel & 1) * 8 + l7) * ROWB + (sel >> 1) * 16);
    const uint32_t boff = (uint32_t)((warp_n * 32 + (sel >> 1) * 8 + l7) * ROWB + (sel & 1) * 16);

    load_stage(0, 0);
    load_stage(1, 1);
    load_stage(2, 2);

    for (int c = 0; c < NCHUNK; c++) {
        const int pend = NCHUNK - 1 - c;
        if (pend >= 2)      asm volatile("cp.async.wait_group 2;" ::: "memory");
        else if (pend == 1) asm volatile("cp.async.wait_group 1;" ::: "memory");
        else                asm volatile("cp.async.wait_group 0;" ::: "memory");
        __syncthreads();

        if (c + 3 < NCHUNK) load_stage((c + 3) & 3, c + 3);

        const uint32_t ds = sbase + (c & 3) * STAGEB;
        const uint32_t sA = ds + 0 * TILEB + aoff;
        const uint32_t sB = ds + 1 * TILEB + boff;

        uint32_t Av[4][4], Bv[4][2];
#pragma unroll
        for (int mt = 0; mt < 4; mt++)
            ldm_x4(Av[mt], sA + mt * (16 * ROWB));
#pragma unroll
        for (int p = 0; p < 2; p++) {
            uint32_t rb[4];
            ldm_x4(rb, sB + p * (16 * ROWB));
            Bv[2 * p][0] = rb[0]; Bv[2 * p][1] = rb[1];
            Bv[2 * p + 1][0] = rb[2]; Bv[2 * p + 1][1] = rb[3];
        }
#pragma unroll
        for (int mt = 0; mt < 4; mt++)
#pragma unroll
            for (int nt = 0; nt < 4; nt++)
                mma16816h(acc[mt][nt], Av[mt], Bv[nt]);
    }
}

// ---- Fused QKV projection: all outputs single fp16 ----
__global__ __launch_bounds__(256, 2) void mma_gemm_qkv(const __half* __restrict__ x,
                                                       const __half* __restrict__ w,
                                                       __half* __restrict__ qq,
                                                       __half* __restrict__ kk,
                                                       __half* __restrict__ vv) {
    extern __shared__ __align__(128) char smem[];
    const uint32_t sbase = smem_u32(smem);
    const int tid = threadIdx.x;
    const int which = blockIdx.x >> 3;
    const int n0 = (blockIdx.x & 7) * BN;
    const int m0 = blockIdx.y * BM;
    const size_t WSZ = (size_t)C_DIM * C_DIM;

    float acc[4][4][4];
#pragma unroll
    for (int i = 0; i < 4; i++)
#pragma unroll
        for (int j = 0; j < 4; j++)
#pragma unroll
            for (int e = 0; e < 4; e++) acc[i][j][e] = 0.0f;

    gemm_mainloop(sbase, tid, x + (size_t)m0 * GK,
                  w + which * WSZ + (size_t)n0 * GK, acc);

    __half* o = (which == 0) ? qq : (which == 1) ? kk : vv;
    const int lane = tid & 31;
    const int warp = tid >> 5;
    const int warp_m = warp >> 2;
    const int warp_n = warp & 3;
    const int er = lane >> 2;
    const int ec = (lane & 3) * 2;
#pragma unroll
    for (int mt = 0; mt < 4; mt++) {
        const int row = m0 + warp_m * 64 + mt * 16 + er;
#pragma unroll
        for (int nt = 0; nt < 4; nt++) {
            const int col = n0 + warp_n * 32 + nt * 8 + ec;
#pragma unroll
            for (int hh = 0; hh < 2; hh++) {
                size_t off = (size_t)(row + 8 * hh) * C_DIM + col;
                *(__half2*)&o[off] =
                    __floats2half2_rn(acc[mt][nt][2 * hh], acc[mt][nt][2 * hh + 1]);
            }
        }
    }
}

// ---- Output projection: fp32 epilogue ----
__global__ __launch_bounds__(256, 2) void mma_gemm_f32(const __half* __restrict__ A,
                                                       const __half* __restrict__ B,
                                                       float* __restrict__ C) {
    extern __shared__ __align__(128) char smem[];
    const uint32_t sbase = smem_u32(smem);
    const int tid = threadIdx.x;
    const int n0 = blockIdx.x * BN;
    const int m0 = blockIdx.y * BM;

    float acc[4][4][4];
#pragma unroll
    for (int i = 0; i < 4; i++)
#pragma unroll
        for (int j = 0; j < 4; j++)
#pragma unroll
            for (int e = 0; e < 4; e++) acc[i][j][e] = 0.0f;

    gemm_mainloop(sbase, tid, A + (size_t)m0 * GK, B + (size_t)n0 * GK, acc);

    const int lane = tid & 31;
    const int warp = tid >> 5;
    const int warp_m = warp >> 2;
    const int warp_n = warp & 3;
    const int er = lane >> 2;
    const int ec = (lane & 3) * 2;
#pragma unroll
    for (int mt = 0; mt < 4; mt++) {
        const int row = m0 + warp_m * 64 + mt * 16 + er;
#pragma unroll
        for (int nt = 0; nt < 4; nt++) {
            const int col = n0 + warp_n * 32 + nt * 8 + ec;
            *(float2*)&C[(size_t)row * C_DIM + col] = make_float2(acc[mt][nt][0], acc[mt][nt][1]);
            *(float2*)&C[(size_t)(row + 8) * C_DIM + col] = make_float2(acc[mt][nt][2], acc[mt][nt][3]);
        }
    }
}

// ---------------------------------------------------------------------------
// Banded causal attention on tensor cores (fp16 single-pass).
// Block = (head, 64-query tile), 256 threads (2x4 warps).
// Phase A: S = Q@K^T (M=64, N=192, K=64), warp tile 32x48.
// Softmax fp32 in smem; P -> fp16 (overlaying S region).
// Phase B: O = P@V (M=64, N=64, K=192), V via ldmatrix.trans.
// ---------------------------------------------------------------------------
#define AROW 144
#define SROW 200
#define PROWB 400

#define OFF_Q  0
#define OFF_K  9216
#define OFF_V  36864
#define OFF_SP 64512
#define ATTN_SMEM 115712

__global__ __launch_bounds__(256, 1) void attn_mma(const __half* __restrict__ qq,
                                                   const __half* __restrict__ kk,
                                                   const __half* __restrict__ vv,
                                                   __half* __restrict__ yy) {
    extern __shared__ __align__(128) char smem[];
    const uint32_t sbase = smem_u32(smem);
    const int h   = blockIdx.y;
    const int t0  = blockIdx.x * 64;
    const int tid = threadIdx.x;
    const int hoff = h * DHEAD;

    for (int idx = tid; idx < 512; idx += 256) {
        int row = idx >> 3, c = idx & 7;
        size_t src = (size_t)(t0 + row) * C_DIM + hoff + c * 8;
        cp16(sbase + OFF_Q + row * AROW + c * 16, qq + src);
    }
    for (int idx = tid; idx < 1536; idx += 256) {
        int row = idx >> 3, c = idx & 7;
        int jg = t0 - BANDW + row;
        uint32_t d = row * AROW + c * 16;
        if (jg >= 0) {
            size_t src = (size_t)jg * C_DIM + hoff + c * 8;
            cp16(sbase + OFF_K + d, kk + src);
            cp16(sbase + OFF_V + d, vv + src);
        } else {
            stz16(sbase + OFF_K + d);
            stz16(sbase + OFF_V + d);
        }
    }
    cp_commit();
    asm volatile("cp.async.wait_group 0;" ::: "memory");
    __syncthreads();

    const int lane = tid & 31;
    const int warp = tid >> 5;
    const int wm = warp >> 2;
    const int wn = warp & 3;
    const int sel = lane >> 3;
    const int l7  = lane & 7;

    float* Sf = (float*)(smem + OFF_SP);

    // ---- Phase A: S = Q@K^T ----
    {
        const uint32_t aoff = (uint32_t)((wm * 32 + (sel & 1) * 8 + l7) * AROW + (sel >> 1) * 16);
        const uint32_t boff = (uint32_t)((wn * 48 + (sel >> 1) * 8 + l7) * AROW + (sel & 1) * 16);
        const uint32_t sQ = sbase + OFF_Q + aoff;
        const uint32_t sK = sbase + OFF_K + boff;

        float acc[2][6][4];
#pragma unroll
        for (int i = 0; i < 2; i++)
#pragma unroll
            for (int j = 0; j < 6; j++)
#pragma unroll
                for (int e = 0; e < 4; e++) acc[i][j][e] = 0.0f;

#pragma unroll
        for (int ks = 0; ks < 4; ks++) {
            const uint32_t ka = ks * 32;
            uint32_t Qv[2][4], Kv[6][2];
#pragma unroll
            for (int mt = 0; mt < 2; mt++)
                ldm_x4(Qv[mt], sQ + mt * (16 * AROW) + ka);
#pragma unroll
            for (int p = 0; p < 3; p++) {
                uint32_t rb[4];
                ldm_x4(rb, sK + p * (16 * AROW) + ka);
                Kv[2 * p][0] = rb[0]; Kv[2 * p][1] = rb[1];
                Kv[2 * p + 1][0] = rb[2]; Kv[2 * p + 1][1] = rb[3];
            }
#pragma unroll
            for (int mt = 0; mt < 2; mt++)
#pragma unroll
                for (int nt = 0; nt < 6; nt++)
                    mma16816h(acc[mt][nt], Qv[mt], Kv[nt]);
        }
        const int er = lane >> 2;
        const int ec = (lane & 3) * 2;
#pragma unroll
        for (int mt = 0; mt < 2; mt++) {
            const int row = wm * 32 + mt * 16 + er;
#pragma unroll
            for (int nt = 0; nt < 6; nt++) {
                const int col = wn * 48 + nt * 8 + ec;
                *(float2*)&Sf[row * SROW + col] = make_float2(acc[mt][nt][0], acc[mt][nt][1]);
                *(float2*)&Sf[(row + 8) * SROW + col] = make_float2(acc[mt][nt][2], acc[mt][nt][3]);
            }
        }
    }
    __syncthreads();

    // ---- softmax ----
    {
        const int qi  = tid >> 2;
        const int sub = tid & 3;
        const int i   = t0 + qi;
        const int j0  = sub * 48;
        float s[48];
        const float4* Srow = (const float4*)(Sf + qi * SROW + j0);
#pragma unroll
        for (int n4 = 0; n4 < 12; n4++) {
            float4 v = Srow[n4];
            s[4 * n4] = v.x; s[4 * n4 + 1] = v.y; s[4 * n4 + 2] = v.z; s[4 * n4 + 3] = v.w;
        }
        float mx = -1e30f;
#pragma unroll
        for (int n = 0; n < 48; n++) {
            int jg = t0 - BANDW + j0 + n;
            bool valid = (jg >= 0) && (jg <= i) && ((i - jg) < BANDW);
            s[n] = valid ? s[n] * 0.125f : -1e30f;
            mx = fmaxf(mx, s[n]);
        }
        mx = fmaxf(mx, __shfl_xor_sync(0xFFFFFFFFu, mx, 1));
        mx = fmaxf(mx, __shfl_xor_sync(0xFFFFFFFFu, mx, 2));
        float sum = 0.0f;
#pragma unroll
        for (int n = 0; n < 48; n++) { s[n] = __expf(s[n] - mx); sum += s[n]; }
        sum += __shfl_xor_sync(0xFFFFFFFFu, sum, 1);
        sum += __shfl_xor_sync(0xFFFFFFFFu, sum, 2);
        float inv = 1.0f / sum;

        __syncthreads();   // all S reads done before P overwrites region

        char* Pb = smem + OFF_SP;
        __half2* Prow = (__half2*)(Pb + qi * PROWB + j0 * 2);
#pragma unroll
        for (int n2 = 0; n2 < 24; n2++)
            Prow[n2] = __floats2half2_rn(s[2 * n2] * inv, s[2 * n2 + 1] * inv);
    }
    __syncthreads();

    // ---- Phase B: O = P@V ----
    {
        const uint32_t aoff = (uint32_t)((wm * 32 + (sel & 1) * 8 + l7) * PROWB + (sel >> 1) * 16);
        const uint32_t voff = (uint32_t)(((sel & 1) * 8 + l7) * AROW + (sel >> 1) * 16 + wn * 32);
        const uint32_t sP = sbase + OFF_SP + aoff;
        const uint32_t sV = sbase + OFF_V + voff;

        float acc[2][2][4];
#pragma unroll
        for (int i = 0; i < 2; i++)
#pragma unroll
            for (int j = 0; j < 2; j++)
#pragma unroll
                for (int e = 0; e < 4; e++) acc[i][j][e] = 0.0f;

#pragma unroll
        for (int ks = 0; ks < 12; ks++) {
            uint32_t Pv[2][4], Vv[2][2];
#pragma unroll
            for (int mt = 0; mt < 2; mt++)
                ldm_x4(Pv[mt], sP + mt * (16 * PROWB) + ks * 32);
            {
                uint32_t rb[4];
                ldm_x4t(rb, sV + ks * (16 * AROW));
                Vv[0][0] = rb[0]; Vv[0][1] = rb[1]; Vv[1][0] = rb[2]; Vv[1][1] = rb[3];
            }
#pragma unroll
            for (int mt = 0; mt < 2; mt++)
#pragma unroll
                for (int nt = 0; nt < 2; nt++)
                    mma16816h(acc[mt][nt], Pv[mt], Vv[nt]);
        }

        const int er = lane >> 2;
        const int ec = (lane & 3) * 2;
#pragma unroll
        for (int mt = 0; mt < 2; mt++) {
            const int row = wm * 32 + mt * 16 + er;
#pragma unroll
            for (int nt = 0; nt < 2; nt++) {
                const int col = wn * 16 + nt * 8 + ec;
#pragma unroll
                for (int hh = 0; hh < 2; hh++) {
                    size_t off = (size_t)(t0 + row + 8 * hh) * C_DIM + hoff + col;
                    *(__half2*)&yy[off] =
                        __floats2half2_rn(acc[mt][nt][2 * hh], acc[mt][nt][2 * hh + 1]);
                }
            }
        }
    }
}

// ---------------------------------------------------------------------------
extern "C" void kernel_launch(void* const* d_in, const int* in_sizes, int n_in,
                              void* d_out, int out_size) {
    const float* x  = (const float*)d_in[0];
    const float* Wq = (const float*)d_in[1];
    const float* Wk = (const float*)d_in[2];
    const float* Wv = (const float*)d_in[3];
    const float* Wo = (const float*)d_in[4];
    float* out = (float*)d_out;

    __half *xh, *qh, *kh, *vh, *ah, *w;
    cudaGetSymbolAddress((void**)&xh, g_x);
    cudaGetSymbolAddress((void**)&qh, g_q);
    cudaGetSymbolAddress((void**)&kh, g_k);
    cudaGetSymbolAddress((void**)&vh, g_v);
    cudaGetSymbolAddress((void**)&ah, g_a);
    cudaGetSymbolAddress((void**)&w, g_w);

    cudaFuncSetAttribute(mma_gemm_qkv, cudaFuncAttributeMaxDynamicSharedMemorySize, GEMM_SMEM);
    cudaFuncSetAttribute(mma_gemm_f32, cudaFuncAttributeMaxDynamicSharedMemorySize, GEMM_SMEM);
    cudaFuncSetAttribute(attn_mma, cudaFuncAttributeMaxDynamicSharedMemorySize, ATTN_SMEM);

    const int NX4 = T_SEQ * C_DIM / 4;
    const int NW4 = C_DIM * C_DIM / 4;
    const size_t WSZ = (size_t)C_DIM * C_DIM;

    conv_x_kernel<<<(NX4 + 255) / 256, 256>>>(x, xh, NX4);
    conv_w4_kernel<<<dim3((NW4 + 255) / 256, 4), 256>>>(Wq, Wk, Wv, Wo, w, NW4);

    mma_gemm_qkv<<<dim3(24, 32), 256, GEMM_SMEM>>>(xh, w, qh, kh, vh);

    attn_mma<<<dim3(T_SEQ / 64, NH), 256, ATTN_SMEM>>>(qh, kh, vh, ah);

    mma_gemm_f32<<<dim3(8, 32), 256, GEMM_SMEM>>>(ah, w + 3 * WSZ, out);
}